// round 10
// baseline (speedup 1.0000x reference)
#include <cuda_runtime.h>
#include <cuda_fp16.h>
#include <math.h>
#include <stdint.h>

// Problem constants
#define BB 256
#define NB 36
#define FI 2048
#define EE 1000
#define HH 1000
#define PP 512
#define K1 3048   // E + F (nonzero cols of x1; h1,h2 zero on step 0)
#define K2 3048   // F + H (nonzero cols of x2; h2 zero)
#define NG 3000   // 3 live gates * H (f gate dead: c_prev = 0)
#define KSPL 4    // split-K factor for skinny GEMMs

// ---------------- scratch ----------------------------------------------------
__device__ __align__(16) __half g_x1h[BB * K1];
__device__ __align__(16) __half g_x2h[BB * K2];
__device__ __align__(16) __half g_h1h[BB * HH];
__device__ __align__(16) __half g_w1h[NG * K1];
__device__ __align__(16) __half g_w2h[NG * K2];
__device__ __align__(16) __half g_wqh[PP * HH];
__device__ __align__(16) __half g_wvh[PP * FI];
__device__ __align__(16) __half g_imgh[BB * NB * FI];
__device__ float g_gates[KSPL * BB * NG];
__device__ float g_q[KSPL * BB * PP];
__device__ float g_vproj[BB * NB * PP];
__device__ float g_mask[BB * NB];          // raw |sum| from img_cvt_mask, then 0/1

// ---------------- fp32 -> fp16 conversion (optionally packing live rows) -----
__global__ void __launch_bounds__(256) cvt_h(
    const float* __restrict__ src, int ld,
    __half* __restrict__ dst,
    int rows, int cols, int remap)            // cols % 4 == 0
{
    int rowq = cols >> 2;
    int total = rows * rowq;
    int stride = gridDim.x * 256;
    for (int idx = blockIdx.x * 256 + threadIdx.x; idx < total; idx += stride) {
        int row = idx / rowq;
        int c4 = (idx - row * rowq) << 2;
        int sr = remap ? (row < 1000 ? row : row + 1000) : row;
        float4 v = *(const float4*)(src + (size_t)sr * ld + c4);
        __half2* d = (__half2*)(dst + (size_t)row * cols + c4);
        d[0] = __floats2half2_rn(v.x, v.y);
        d[1] = __floats2half2_rn(v.z, v.w);
    }
}

// -------- img fp32->fp16 + per-row |sum| (one block per (b,n) row) -----------
__global__ void __launch_bounds__(256) img_cvt_mask(const float* __restrict__ img)
{
    int r = blockIdx.x;                 // 0 .. B*NB-1
    int tid = threadIdx.x;
    int lane = tid & 31, warp = tid >> 5;
    __shared__ float red[8];

    const float* row = img + (size_t)r * FI;
    float4 v0 = *(const float4*)(row + tid * 8);
    float4 v1 = *(const float4*)(row + tid * 8 + 4);
    float s = fabsf(v0.x) + fabsf(v0.y) + fabsf(v0.z) + fabsf(v0.w)
            + fabsf(v1.x) + fabsf(v1.y) + fabsf(v1.z) + fabsf(v1.w);

    __half2 h0 = __floats2half2_rn(v0.x, v0.y);
    __half2 h1 = __floats2half2_rn(v0.z, v0.w);
    __half2 h2 = __floats2half2_rn(v1.x, v1.y);
    __half2 h3 = __floats2half2_rn(v1.z, v1.w);
    uint4 u;
    u.x = *(uint32_t*)&h0; u.y = *(uint32_t*)&h1;
    u.z = *(uint32_t*)&h2; u.w = *(uint32_t*)&h3;
    *(uint4*)(g_imgh + (size_t)r * FI + tid * 8) = u;

#pragma unroll
    for (int off = 16; off > 0; off >>= 1)
        s += __shfl_xor_sync(0xffffffffu, s, off);
    if (lane == 0) red[warp] = s;
    __syncthreads();
    if (tid == 0) {
        float t = 0.f;
#pragma unroll
        for (int w = 0; w < 8; ++w) t += red[w];
        g_mask[r] = t;
    }
}

// -------- masked mean pool from imgh + x1h build (one block per b) ------------
__global__ void __launch_bounds__(256) pool_build(const float* __restrict__ emb)
{
    int b = blockIdx.x;
    int tid = threadIdx.x;
    __shared__ float mk[NB];

    if (tid < NB) {
        float m = (g_mask[b * NB + tid] > 0.f) ? 1.f : 0.f;
        mk[tid] = m;
        g_mask[b * NB + tid] = m;      // binarized for attn
    }
    __syncthreads();

    float cnt = 0.f;
#pragma unroll
    for (int n = 0; n < NB; ++n) cnt += mk[n];
    float inv = 1.f / fmaxf(cnt, 1e-13f);

    float acc[8];
#pragma unroll
    for (int j = 0; j < 8; ++j) acc[j] = 0.f;

    const __half2* baseh2 = (const __half2*)(g_imgh + (size_t)b * NB * FI);
    for (int n = 0; n < NB; ++n) {
        if (mk[n] == 0.f) continue;    // uniform branch per block
        const __half2* rh = baseh2 + (size_t)n * (FI / 2) + tid * 4;
#pragma unroll
        for (int j = 0; j < 4; ++j) {
            float2 v = __half22float2(rh[j]);
            acc[2 * j]     += v.x;
            acc[2 * j + 1] += v.y;
        }
    }

    __half* x1 = g_x1h + (size_t)b * K1;
    __half2 o0 = __floats2half2_rn(acc[0] * inv, acc[1] * inv);
    __half2 o1 = __floats2half2_rn(acc[2] * inv, acc[3] * inv);
    __half2 o2 = __floats2half2_rn(acc[4] * inv, acc[5] * inv);
    __half2 o3 = __floats2half2_rn(acc[6] * inv, acc[7] * inv);
    uint4 u;
    u.x = *(uint32_t*)&o0; u.y = *(uint32_t*)&o1;
    u.z = *(uint32_t*)&o2; u.w = *(uint32_t*)&o3;
    *(uint4*)(x1 + EE + tid * 8) = u;   // EE*2 = 2000 bytes, 16B aligned
    for (int j = tid; j < EE; j += 256)
        x1[j] = __float2half(emb[(size_t)b * EE + j]);
}

// ========== fp16 tensor GEMM (A fp16): C(+split) = A * B^T (+bias) ===========
#define H_SMEM (2 * (4096 + 4096) * 2)   // 32 KB

__device__ __forceinline__ void mma_h(float* c, const uint32_t* a, const uint32_t* b) {
    asm volatile(
        "mma.sync.aligned.m16n8k16.row.col.f32.f16.f16.f32 "
        "{%0,%1,%2,%3}, {%4,%5,%6,%7}, {%8,%9}, {%0,%1,%2,%3};"
        : "+f"(c[0]), "+f"(c[1]), "+f"(c[2]), "+f"(c[3])
        : "r"(a[0]), "r"(a[1]), "r"(a[2]), "r"(a[3]), "r"(b[0]), "r"(b[1]));
}

// shared compute + epilogue used by both GEMM variants
#define GEMM_COMPUTE_EPILOGUE                                                     \
    for (int kt = 0; kt < nk; ++kt) {                                             \
        asm volatile("cp.async.wait_group 0;");                                   \
        __syncthreads();                                                          \
        GEMM_PREFETCH_NEXT                                                        \
        const int bo = (kt & 1) * 4096;                                           \
        _Pragma("unroll")                                                         \
        for (int s = 0; s < 2; ++s) {                                             \
            uint32_t a[4][4], b[4][2];                                            \
            _Pragma("unroll")                                                     \
            for (int mt = 0; mt < 4; ++mt) {                                      \
                int row = wm * 64 + mt * 16 + arl;                                \
                int sv = (2 * s + alv) ^ ((row >> 1) & 3);                        \
                uint32_t ad = sbase + (uint32_t)(bo + row * 32 + sv * 8) * 2;     \
                asm volatile(                                                     \
                    "ldmatrix.sync.aligned.m8n8.x4.shared.b16 {%0,%1,%2,%3}, [%4];"\
                    : "=r"(a[mt][0]), "=r"(a[mt][1]), "=r"(a[mt][2]), "=r"(a[mt][3])\
                    : "r"(ad));                                                   \
            }                                                                     \
            _Pragma("unroll")                                                     \
            for (int p = 0; p < 2; ++p) {                                         \
                int row = wn * 32 + p * 16 + brl;                                 \
                int sv = (2 * s + blv) ^ ((row >> 1) & 3);                        \
                uint32_t ad = sbase + (uint32_t)(8192 + bo + row * 32 + sv * 8) * 2;\
                uint32_t r0, r1, r2, r3;                                          \
                asm volatile(                                                     \
                    "ldmatrix.sync.aligned.m8n8.x4.shared.b16 {%0,%1,%2,%3}, [%4];"\
                    : "=r"(r0), "=r"(r1), "=r"(r2), "=r"(r3) : "r"(ad));          \
                b[p * 2][0] = r0;     b[p * 2][1] = r1;                           \
                b[p * 2 + 1][0] = r2; b[p * 2 + 1][1] = r3;                       \
            }                                                                     \
            _Pragma("unroll")                                                     \
            for (int mt = 0; mt < 4; ++mt)                                        \
                _Pragma("unroll")                                                 \
                for (int nt = 0; nt < 4; ++nt)                                    \
                    mma_h(acc[mt][nt], a[mt], b[nt]);                             \
        }                                                                         \
        GEMM_STORE_NEXT                                                           \
    }                                                                             \
    const int g = lane >> 2, tg = lane & 3;                                       \
    const bool addb = (bias != nullptr) && (kz == 0);                             \
    _Pragma("unroll")                                                             \
    for (int mt = 0; mt < 4; ++mt) {                                              \
        int r0 = m0 + wm * 64 + mt * 16 + g;                                      \
        int r1 = r0 + 8;                                                          \
        _Pragma("unroll")                                                         \
        for (int nt = 0; nt < 4; ++nt) {                                          \
            int col = n0 + wn * 32 + nt * 8 + tg * 2;                             \
            if (col >= N) continue;                                               \
            float b0 = addb ? bias[col]     : 0.f;                                \
            float b1 = addb ? bias[col + 1] : 0.f;                                \
            *(float2*)&C[(size_t)r0 * ldc + col] =                                \
                make_float2(acc[mt][nt][0] + b0, acc[mt][nt][1] + b1);            \
            *(float2*)&C[(size_t)r1 * ldc + col] =                                \
                make_float2(acc[mt][nt][2] + b0, acc[mt][nt][3] + b1);            \
        }                                                                         \
    }

__global__ void __launch_bounds__(256, 2) gemm_h(
    const __half* __restrict__ A, int lda,
    const __half* __restrict__ B, int ldb,
    const float* __restrict__ bias,
    float* __restrict__ C, int ldc, size_t cstride,
    int N, int K, int ksplit)
{
    extern __shared__ __half sh[];
    const int tid  = threadIdx.x;
    const int lane = tid & 31;
    const int warp = tid >> 5;
    const int wm   = warp >> 2;
    const int wn   = warp & 3;
    const int m0   = blockIdx.y * 128;
    const int n0   = blockIdx.x * 128;
    const int kz   = blockIdx.z;
    const int Kst  = kz * ksplit;
    const int Kend = min(K, Kst + ksplit);
    const int nk   = (Kend - Kst + 31) >> 5;
    C += (size_t)kz * cstride;
    const uint32_t sbase = (uint32_t)__cvta_generic_to_shared(sh);

    auto load_tile = [&](int kt, int buf) {
        const int k0 = Kst + kt * 32;
#pragma unroll
        for (int i = 0; i < 2; ++i) {
            int idx = i * 256 + tid;
            int row = idx >> 2, v = idx & 3;
            int sv = v ^ ((row >> 1) & 3);
            int k = k0 + v * 8;
            {
                uint32_t dst = sbase + (uint32_t)(buf * 4096 + row * 32 + sv * 8) * 2;
                const __half* src = A + (size_t)(m0 + row) * lda + (k < Kend ? k : 0);
                int sz = (k < Kend) ? 16 : 0;
                asm volatile("cp.async.cg.shared.global [%0], [%1], 16, %2;\n"
                             :: "r"(dst), "l"(src), "r"(sz));
            }
            {
                int bn = n0 + row;
                uint32_t dst = sbase + (uint32_t)(8192 + buf * 4096 + row * 32 + sv * 8) * 2;
                const __half* src = B + (size_t)(bn < N ? bn : 0) * ldb + (k < Kend ? k : 0);
                int sz = (k < Kend && bn < N) ? 16 : 0;
                asm volatile("cp.async.cg.shared.global [%0], [%1], 16, %2;\n"
                             :: "r"(dst), "l"(src), "r"(sz));
            }
        }
        asm volatile("cp.async.commit_group;");
    };

    float acc[4][4][4];
#pragma unroll
    for (int mt = 0; mt < 4; ++mt)
#pragma unroll
        for (int nt = 0; nt < 4; ++nt)
#pragma unroll
            for (int i = 0; i < 4; ++i) acc[mt][nt][i] = 0.f;

    const int arl = lane & 15;
    const int alv = lane >> 4;
    const int brl = (lane & 7) + ((lane >> 4) << 3);
    const int blv = (lane >> 3) & 1;

    load_tile(0, 0);

#define GEMM_PREFETCH_NEXT  if (kt + 1 < nk) load_tile(kt + 1, (kt + 1) & 1);
#define GEMM_STORE_NEXT
    GEMM_COMPUTE_EPILOGUE
#undef GEMM_PREFETCH_NEXT
#undef GEMM_STORE_NEXT
}

// ===== fp16 GEMM variant with A in fp32 (cvt at STS): vproj without pre-cvt ==
__global__ void __launch_bounds__(256, 2) gemm_hf(
    const float* __restrict__ Af, int lda,
    const __half* __restrict__ B, int ldb,
    const float* __restrict__ bias,
    float* __restrict__ C, int ldc,
    int N, int K)
{
    extern __shared__ __half sh[];
    const int tid  = threadIdx.x;
    const int lane = tid & 31;
    const int warp = tid >> 5;
    const int wm   = warp >> 2;
    const int wn   = warp & 3;
    const int m0   = blockIdx.y * 128;
    const int n0   = blockIdx.x * 128;
    const int kz   = 0;
    const int nk   = K >> 5;               // K % 32 == 0 (vproj: 2048)
    const uint32_t sbase = (uint32_t)__cvta_generic_to_shared(sh);

    float4 fa[2][2];   // A staging: 2 chunks x 8 floats

    auto ldgA = [&](int kt) {
        const int k0 = kt * 32;
#pragma unroll
        for (int i = 0; i < 2; ++i) {
            int idx = i * 256 + tid;
            int row = idx >> 2, v = idx & 3;
            const float* src = Af + (size_t)(m0 + row) * lda + k0 + v * 8;
            fa[i][0] = *(const float4*)(src);
            fa[i][1] = *(const float4*)(src + 4);
        }
    };
    auto stsA = [&](int buf) {
#pragma unroll
        for (int i = 0; i < 2; ++i) {
            int idx = i * 256 + tid;
            int row = idx >> 2, v = idx & 3;
            int sv = v ^ ((row >> 1) & 3);
            __half2 h0 = __floats2half2_rn(fa[i][0].x, fa[i][0].y);
            __half2 h1 = __floats2half2_rn(fa[i][0].z, fa[i][0].w);
            __half2 h2 = __floats2half2_rn(fa[i][1].x, fa[i][1].y);
            __half2 h3 = __floats2half2_rn(fa[i][1].z, fa[i][1].w);
            uint4 u;
            u.x = *(uint32_t*)&h0; u.y = *(uint32_t*)&h1;
            u.z = *(uint32_t*)&h2; u.w = *(uint32_t*)&h3;
            *(uint4*)(sh + buf * 4096 + row * 32 + sv * 8) = u;
        }
    };
    auto cpB = [&](int kt, int buf) {
        const int k0 = kt * 32;
#pragma unroll
        for (int i = 0; i < 2; ++i) {
            int idx = i * 256 + tid;
            int row = idx >> 2, v = idx & 3;
            int sv = v ^ ((row >> 1) & 3);
            int k = k0 + v * 8;
            int bn = n0 + row;
            uint32_t dst = sbase + (uint32_t)(8192 + buf * 4096 + row * 32 + sv * 8) * 2;
            const __half* src = B + (size_t)(bn < N ? bn : 0) * ldb + k;
            int sz = (bn < N) ? 16 : 0;
            asm volatile("cp.async.cg.shared.global [%0], [%1], 16, %2;\n"
                         :: "r"(dst), "l"(src), "r"(sz));
        }
        asm volatile("cp.async.commit_group;");
    };

    float acc[4][4][4];
#pragma unroll
    for (int mt = 0; mt < 4; ++mt)
#pragma unroll
        for (int nt = 0; nt < 4; ++nt)
#pragma unroll
            for (int i = 0; i < 4; ++i) acc[mt][nt][i] = 0.f;

    const int arl = lane & 15;
    const int alv = lane >> 4;
    const int brl = (lane & 7) + ((lane >> 4) << 3);
    const int blv = (lane >> 3) & 1;

    ldgA(0); cpB(0, 0); stsA(0);

#define GEMM_PREFETCH_NEXT  if (kt + 1 < nk) { ldgA(kt + 1); cpB(kt + 1, (kt + 1) & 1); }
#define GEMM_STORE_NEXT     if (kt + 1 < nk) stsA((kt + 1) & 1);
    GEMM_COMPUTE_EPILOGUE
#undef GEMM_PREFETCH_NEXT
#undef GEMM_STORE_NEXT
}

// ---------------- LSTM pointwise (c_prev = 0), sums KSPL partials ------------
__device__ __forceinline__ float sigf(float x) { return 1.f / (1.f + expf(-x)); }

__global__ void __launch_bounds__(256) lstm_pointwise4(
    const float* __restrict__ gp,
    const float* __restrict__ b_ih,
    const float* __restrict__ b_hh,
    float* __restrict__ houtf,
    __half* __restrict__ houth)
{
    int idx = blockIdx.x * 256 + threadIdx.x;
    if (idx >= BB * HH) return;
    int b = idx / HH, j = idx - b * HH;
    float gi = 0.f, gg = 0.f, go = 0.f;
#pragma unroll
    for (int z = 0; z < KSPL; ++z) {
        const float* g = gp + (size_t)z * BB * NG + (size_t)b * NG;
        gi += g[j];
        gg += g[HH + j];
        go += g[2 * HH + j];
    }
    gi += b_ih[j]          + b_hh[j];
    gg += b_ih[2 * HH + j] + b_hh[2 * HH + j];
    go += b_ih[3 * HH + j] + b_hh[3 * HH + j];
    float c = sigf(gi) * tanhf(gg);
    float h = sigf(go) * tanhf(c);
    if (houtf) houtf[idx] = h;
    if (houth) houth[idx] = __float2half(h);
}

// ------- scores -> masked softmax -> attended (from imgh) -> x2h -------------
__global__ void __launch_bounds__(128) attn_kernel(const float* __restrict__ wa)
{
    int b = blockIdx.x;
    int tid = threadIdx.x;
    int warp = tid >> 5, lane = tid & 31;
    __shared__ float sc[NB];
    __shared__ float at[NB];
    __shared__ float qb[PP];

    for (int p = tid; p < PP; p += 128) {
        float s = 0.f;
#pragma unroll
        for (int z = 0; z < KSPL; ++z)
            s += g_q[(size_t)z * BB * PP + (size_t)b * PP + p];
        qb[p] = s;
    }
    __syncthreads();

    for (int n = warp; n < NB; n += 4) {
        const float* vp = g_vproj + ((size_t)b * NB + n) * PP;
        float s = 0.f;
        for (int p = lane; p < PP; p += 32)
            s += tanhf(qb[p] + vp[p]) * wa[p];
#pragma unroll
        for (int off = 16; off > 0; off >>= 1)
            s += __shfl_xor_sync(0xffffffffu, s, off);
        if (lane == 0)
            sc[n] = (g_mask[b * NB + n] > 0.f) ? s : -1e9f;
    }
    __syncthreads();

    if (tid == 0) {
        float m = -INFINITY;
        for (int n = 0; n < NB; ++n) m = fmaxf(m, sc[n]);
        float sum = 0.f;
        for (int n = 0; n < NB; ++n) { float e = expf(sc[n] - m); at[n] = e; sum += e; }
        float inv = 1.f / sum;
        for (int n = 0; n < NB; ++n) at[n] *= inv;
    }
    __syncthreads();

    __half* x2 = g_x2h + (size_t)b * K2;
    const __half2* baseh2 = (const __half2*)(g_imgh + (size_t)b * NB * FI);
    for (int f2 = tid; f2 < FI / 2; f2 += 128) {
        float ax = 0.f, ay = 0.f;
#pragma unroll 4
        for (int n = 0; n < NB; ++n) {
            float2 v = __half22float2(baseh2[(size_t)n * (FI / 2) + f2]);
            ax = fmaf(at[n], v.x, ax);
            ay = fmaf(at[n], v.y, ay);
        }
        ((__half2*)x2)[f2] = __floats2half2_rn(ax, ay);
    }
    for (int j = tid; j < HH; j += 128)
        x2[FI + j] = g_h1h[(size_t)b * HH + j];
}

// ---------------- host launcher ----------------------------------------------
extern "C" void kernel_launch(void* const* d_in, const int* in_sizes, int n_in,
                              void* d_out, int out_size)
{
    const float* img   = (const float*)d_in[0];
    const float* emb   = (const float*)d_in[1];
    const float* W_ih1 = (const float*)d_in[2];
    const float* b_ih1 = (const float*)d_in[3];
    const float* b_hh1 = (const float*)d_in[5];
    const float* Wq    = (const float*)d_in[6];
    const float* bq    = (const float*)d_in[7];
    const float* Wv    = (const float*)d_in[8];
    const float* bv    = (const float*)d_in[9];
    const float* wa    = (const float*)d_in[10];
    const float* W_ih2 = (const float*)d_in[11];
    const float* b_ih2 = (const float*)d_in[12];
    const float* b_hh2 = (const float*)d_in[14];
    float* out = (float*)d_out;

    float *p_g, *p_q, *p_v;
    __half *p_x1, *p_x2, *p_h1, *p_w1, *p_w2, *p_wq, *p_wv;
    cudaGetSymbolAddress((void**)&p_g,   g_gates);
    cudaGetSymbolAddress((void**)&p_q,   g_q);
    cudaGetSymbolAddress((void**)&p_v,   g_vproj);
    cudaGetSymbolAddress((void**)&p_x1,  g_x1h);
    cudaGetSymbolAddress((void**)&p_x2,  g_x2h);
    cudaGetSymbolAddress((void**)&p_h1,  g_h1h);
    cudaGetSymbolAddress((void**)&p_w1,  g_w1h);
    cudaGetSymbolAddress((void**)&p_w2,  g_w2h);
    cudaGetSymbolAddress((void**)&p_wq,  g_wqh);
    cudaGetSymbolAddress((void**)&p_wv,  g_wvh);

    cudaFuncSetAttribute(gemm_h,  cudaFuncAttributeMaxDynamicSharedMemorySize, H_SMEM);
    cudaFuncSetAttribute(gemm_hf, cudaFuncAttributeMaxDynamicSharedMemorySize, H_SMEM);

    static cudaStream_t s2 = nullptr, s3 = nullptr;
    static cudaEvent_t evF = nullptr, evPool = nullptr, evV = nullptr,
                       evWQ = nullptr, evW2 = nullptr, evImg = nullptr;
    if (!s2) {
        cudaStreamCreateWithFlags(&s2, cudaStreamNonBlocking);
        cudaStreamCreateWithFlags(&s3, cudaStreamNonBlocking);
        cudaEventCreateWithFlags(&evF,    cudaEventDisableTiming);
        cudaEventCreateWithFlags(&evPool, cudaEventDisableTiming);
        cudaEventCreateWithFlags(&evV,    cudaEventDisableTiming);
        cudaEventCreateWithFlags(&evWQ,   cudaEventDisableTiming);
        cudaEventCreateWithFlags(&evW2,   cudaEventDisableTiming);
        cudaEventCreateWithFlags(&evImg,  cudaEventDisableTiming);
    }

    cudaEventRecord(evF, 0);
    cudaStreamWaitEvent(s2, evF, 0);
    cudaStreamWaitEvent(s3, evF, 0);

    // --- s2: Wv cvt -> vproj (A = img fp32, converted in-kernel) ---
    cvt_h<<<512, 256, 0, s2>>>(Wv, FI, p_wv, PP, FI, 0);
    {   // vproj = img @ wvh^T + bv : 9216 x 512 x 2048
        dim3 grid(PP / 128, (BB * NB) / 128, 1);
        gemm_hf<<<grid, 256, H_SMEM, s2>>>(img, FI, p_wv, FI, bv, p_v, PP, PP, FI);
    }
    cudaEventRecord(evV, s2);

    // --- s3: img cvt+mask -> pool/x1h ; Wq, W2 cvts ---
    img_cvt_mask<<<BB * NB, 256, 0, s3>>>(img);
    cudaEventRecord(evImg, s3);
    pool_build<<<BB, 256, 0, s3>>>(emb);
    cudaEventRecord(evPool, s3);
    cvt_h<<<512, 256, 0, s3>>>(Wq, HH, p_wq, PP, HH, 0);
    cudaEventRecord(evWQ, s3);
    cvt_h<<<2048, 256, 0, s3>>>(W_ih2, FI + 2 * HH, p_w2, NG, K2, 1);
    cudaEventRecord(evW2, s3);

    // --- main chain ---
    cvt_h<<<2048, 256>>>(W_ih1, EE + FI + 2 * HH, p_w1, NG, K1, 1);

    cudaStreamWaitEvent(0, evPool, 0);
    {   // gates1 = x1h @ w1h^T : 256 x 3000 x 3048, split-K 4
        dim3 grid((NG + 127) / 128, BB / 128, KSPL);
        gemm_h<<<grid, 256, H_SMEM>>>(p_x1, K1, p_w1, K1, nullptr,
                                      p_g, NG, (size_t)BB * NG, NG, K1, 768);
    }
    lstm_pointwise4<<<(BB * HH + 255) / 256, 256>>>(p_g, b_ih1, b_hh1,
                                                    nullptr, p_h1);

    cudaStreamWaitEvent(0, evWQ, 0);
    {   // q = h1h @ wqh^T + bq : 256 x 512 x 1000, split-K 4
        dim3 grid(PP / 128, BB / 128, KSPL);
        gemm_h<<<grid, 256, H_SMEM>>>(p_h1, HH, p_wq, HH, bq,
                                      p_q, PP, (size_t)BB * PP, PP, HH, 256);
    }

    cudaStreamWaitEvent(0, evV, 0);
    cudaStreamWaitEvent(0, evImg, 0);
    attn_kernel<<<BB, 128>>>(wa);

    cudaStreamWaitEvent(0, evW2, 0);
    {   // gates2 = x2h @ w2h^T : 256 x 3000 x 3048, split-K 4
        dim3 grid((NG + 127) / 128, BB / 128, KSPL);
        gemm_h<<<grid, 256, H_SMEM>>>(p_x2, K2, p_w2, K2, nullptr,
                                      p_g, NG, (size_t)BB * NG, NG, K2, 768);
    }
    lstm_pointwise4<<<(BB * HH + 255) / 256, 256>>>(p_g, b_ih2, b_hh2,
                                                    out, nullptr);
}

// round 11
// speedup vs baseline: 1.0767x; 1.0767x over previous
#include <cuda_runtime.h>
#include <cuda_fp16.h>
#include <math.h>
#include <stdint.h>

// Problem constants
#define BB 256
#define NB 36
#define FI 2048
#define EE 1000
#define HH 1000
#define PP 512
#define K1 3048   // E + F (nonzero cols of x1; h1,h2 zero on step 0)
#define K2 3048   // F + H (nonzero cols of x2; h2 zero)
#define NG 3000   // 3 live gates * H (f gate dead: c_prev = 0)
#define KSPL 4    // split-K factor for skinny GEMMs

// ---------------- scratch ----------------------------------------------------
__device__ __align__(16) __half g_x1h[BB * K1];
__device__ __align__(16) __half g_x2h[BB * K2];
__device__ __align__(16) __half g_h1h[BB * HH];
__device__ __align__(16) __half g_w1h[NG * K1];
__device__ __align__(16) __half g_w2h[NG * K2];
__device__ __align__(16) __half g_wqh[PP * HH];
__device__ __align__(16) __half g_wvh[PP * FI];
__device__ __align__(16) __half g_imgh[BB * NB * FI];
__device__ float g_gates[KSPL * BB * NG];
__device__ float g_q[KSPL * BB * PP];
__device__ float g_vproj[BB * NB * PP];
__device__ float g_mask[BB * NB];          // raw |sum|, then binarized 0/1

// ---------------- fp32 -> fp16 conversion (optionally packing live rows) -----
__global__ void __launch_bounds__(256) cvt_h(
    const float* __restrict__ src, int ld,
    __half* __restrict__ dst,
    int rows, int cols, int remap)            // cols % 4 == 0
{
    int rowq = cols >> 2;
    int total = rows * rowq;
    int stride = gridDim.x * 256;
    for (int idx = blockIdx.x * 256 + threadIdx.x; idx < total; idx += stride) {
        int row = idx / rowq;
        int c4 = (idx - row * rowq) << 2;
        int sr = remap ? (row < 1000 ? row : row + 1000) : row;
        float4 v = *(const float4*)(src + (size_t)sr * ld + c4);
        __half2* d = (__half2*)(dst + (size_t)row * cols + c4);
        d[0] = __floats2half2_rn(v.x, v.y);
        d[1] = __floats2half2_rn(v.z, v.w);
    }
}

// -------- img fp32->fp16 + per-row |sum| (one block per (b,n) row) -----------
// The ONLY reader of the fp32 image tensor.
__global__ void __launch_bounds__(256) img_cvt_mask(const float* __restrict__ img)
{
    int r = blockIdx.x;                 // 0 .. B*NB-1
    int tid = threadIdx.x;
    int lane = tid & 31, warp = tid >> 5;
    __shared__ float red[8];

    const float* row = img + (size_t)r * FI;
    float4 v0 = *(const float4*)(row + tid * 8);
    float4 v1 = *(const float4*)(row + tid * 8 + 4);
    float s = fabsf(v0.x) + fabsf(v0.y) + fabsf(v0.z) + fabsf(v0.w)
            + fabsf(v1.x) + fabsf(v1.y) + fabsf(v1.z) + fabsf(v1.w);

    __half2 h0 = __floats2half2_rn(v0.x, v0.y);
    __half2 h1 = __floats2half2_rn(v0.z, v0.w);
    __half2 h2 = __floats2half2_rn(v1.x, v1.y);
    __half2 h3 = __floats2half2_rn(v1.z, v1.w);
    uint4 u;
    u.x = *(uint32_t*)&h0; u.y = *(uint32_t*)&h1;
    u.z = *(uint32_t*)&h2; u.w = *(uint32_t*)&h3;
    *(uint4*)(g_imgh + (size_t)r * FI + tid * 8) = u;

#pragma unroll
    for (int off = 16; off > 0; off >>= 1)
        s += __shfl_xor_sync(0xffffffffu, s, off);
    if (lane == 0) red[warp] = s;
    __syncthreads();
    if (tid == 0) {
        float t = 0.f;
#pragma unroll
        for (int w = 0; w < 8; ++w) t += red[w];
        g_mask[r] = t;
    }
}

// -------- masked mean pool from imgh + x1h build; grid (B, 4) -----------------
// Each block handles one 512-feature chunk of one batch element.
__global__ void __launch_bounds__(256) pool_build(const float* __restrict__ emb)
{
    int b = blockIdx.x;
    int chunk = blockIdx.y;             // 0..3
    int tid = threadIdx.x;
    __shared__ float mk[NB];

    if (tid < NB) {
        float m = (g_mask[b * NB + tid] > 0.f) ? 1.f : 0.f;
        mk[tid] = m;
        if (chunk == 0) g_mask[b * NB + tid] = m;   // binarize for attn (>0 invariant)
    }
    __syncthreads();

    float cnt = 0.f;
#pragma unroll
    for (int n = 0; n < NB; ++n) cnt += mk[n];
    float inv = 1.f / fmaxf(cnt, 1e-13f);

    const __half2* baseh2 = (const __half2*)(g_imgh + (size_t)b * NB * FI);
    int f2 = chunk * 256 + tid;         // half2 index, 0..1023
    float ax = 0.f, ay = 0.f;
#pragma unroll 6
    for (int n = 0; n < NB; ++n) {
        float2 v = __half22float2(baseh2[(size_t)n * (FI / 2) + f2]);
        ax = fmaf(mk[n], v.x, ax);
        ay = fmaf(mk[n], v.y, ay);
    }

    __half* x1 = g_x1h + (size_t)b * K1;
    ((__half2*)(x1 + EE))[f2] = __floats2half2_rn(ax * inv, ay * inv);

    int j = chunk * 256 + tid;          // 4*256 = 1024 >= EE
    if (j < EE) x1[j] = __float2half(emb[(size_t)b * EE + j]);
}

// ========== fp16 tensor GEMM: C(+split) = A[M,K] * B[N,K]^T (+bias) ==========
#define H_SMEM (2 * (4096 + 4096) * 2)   // 32 KB

__device__ __forceinline__ void mma_h(float* c, const uint32_t* a, const uint32_t* b) {
    asm volatile(
        "mma.sync.aligned.m16n8k16.row.col.f32.f16.f16.f32 "
        "{%0,%1,%2,%3}, {%4,%5,%6,%7}, {%8,%9}, {%0,%1,%2,%3};"
        : "+f"(c[0]), "+f"(c[1]), "+f"(c[2]), "+f"(c[3])
        : "r"(a[0]), "r"(a[1]), "r"(a[2]), "r"(a[3]), "r"(b[0]), "r"(b[1]));
}

__global__ void __launch_bounds__(256, 2) gemm_h(
    const __half* __restrict__ A, int lda,
    const __half* __restrict__ B, int ldb,
    const float* __restrict__ bias,
    float* __restrict__ C, int ldc, size_t cstride,
    int N, int K, int ksplit)
{
    extern __shared__ __half sh[];   // A buf0 @0, A buf1 @4096, B @8192+
    const int tid  = threadIdx.x;
    const int lane = tid & 31;
    const int warp = tid >> 5;
    const int wm   = warp >> 2;
    const int wn   = warp & 3;
    const int m0   = blockIdx.y * 128;
    const int n0   = blockIdx.x * 128;
    const int kz   = blockIdx.z;
    const int Kst  = kz * ksplit;
    const int Kend = min(K, Kst + ksplit);
    const int nk   = (Kend - Kst + 31) >> 5;
    C += (size_t)kz * cstride;
    const uint32_t sbase = (uint32_t)__cvta_generic_to_shared(sh);

    auto load_tile = [&](int kt, int buf) {
        const int k0 = Kst + kt * 32;
#pragma unroll
        for (int i = 0; i < 2; ++i) {
            int idx = i * 256 + tid;
            int row = idx >> 2, v = idx & 3;
            int sv = v ^ ((row >> 1) & 3);
            int k = k0 + v * 8;
            {
                uint32_t dst = sbase + (uint32_t)(buf * 4096 + row * 32 + sv * 8) * 2;
                const __half* src = A + (size_t)(m0 + row) * lda + (k < Kend ? k : 0);
                int sz = (k < Kend) ? 16 : 0;
                asm volatile("cp.async.cg.shared.global [%0], [%1], 16, %2;\n"
                             :: "r"(dst), "l"(src), "r"(sz));
            }
            {
                int bn = n0 + row;
                uint32_t dst = sbase + (uint32_t)(8192 + buf * 4096 + row * 32 + sv * 8) * 2;
                const __half* src = B + (size_t)(bn < N ? bn : 0) * ldb + (k < Kend ? k : 0);
                int sz = (k < Kend && bn < N) ? 16 : 0;
                asm volatile("cp.async.cg.shared.global [%0], [%1], 16, %2;\n"
                             :: "r"(dst), "l"(src), "r"(sz));
            }
        }
        asm volatile("cp.async.commit_group;");
    };

    float acc[4][4][4];
#pragma unroll
    for (int mt = 0; mt < 4; ++mt)
#pragma unroll
        for (int nt = 0; nt < 4; ++nt)
#pragma unroll
            for (int i = 0; i < 4; ++i) acc[mt][nt][i] = 0.f;

    const int arl = lane & 15;
    const int alv = lane >> 4;
    const int brl = (lane & 7) + ((lane >> 4) << 3);
    const int blv = (lane >> 3) & 1;

    load_tile(0, 0);

    for (int kt = 0; kt < nk; ++kt) {
        asm volatile("cp.async.wait_group 0;");
        __syncthreads();
        if (kt + 1 < nk) load_tile(kt + 1, (kt + 1) & 1);

        const int bo = (kt & 1) * 4096;
#pragma unroll
        for (int s = 0; s < 2; ++s) {
            uint32_t a[4][4], b[4][2];
#pragma unroll
            for (int mt = 0; mt < 4; ++mt) {
                int row = wm * 64 + mt * 16 + arl;
                int sv = (2 * s + alv) ^ ((row >> 1) & 3);
                uint32_t ad = sbase + (uint32_t)(bo + row * 32 + sv * 8) * 2;
                asm volatile(
                    "ldmatrix.sync.aligned.m8n8.x4.shared.b16 {%0,%1,%2,%3}, [%4];"
                    : "=r"(a[mt][0]), "=r"(a[mt][1]), "=r"(a[mt][2]), "=r"(a[mt][3])
                    : "r"(ad));
            }
#pragma unroll
            for (int p = 0; p < 2; ++p) {
                int row = wn * 32 + p * 16 + brl;
                int sv = (2 * s + blv) ^ ((row >> 1) & 3);
                uint32_t ad = sbase + (uint32_t)(8192 + bo + row * 32 + sv * 8) * 2;
                uint32_t r0, r1, r2, r3;
                asm volatile(
                    "ldmatrix.sync.aligned.m8n8.x4.shared.b16 {%0,%1,%2,%3}, [%4];"
                    : "=r"(r0), "=r"(r1), "=r"(r2), "=r"(r3) : "r"(ad));
                b[p * 2][0] = r0;     b[p * 2][1] = r1;
                b[p * 2 + 1][0] = r2; b[p * 2 + 1][1] = r3;
            }
#pragma unroll
            for (int mt = 0; mt < 4; ++mt)
#pragma unroll
                for (int nt = 0; nt < 4; ++nt)
                    mma_h(acc[mt][nt], a[mt], b[nt]);
        }
    }

    const int g = lane >> 2, tg = lane & 3;
    const bool addb = (bias != nullptr) && (kz == 0);
#pragma unroll
    for (int mt = 0; mt < 4; ++mt) {
        int r0 = m0 + wm * 64 + mt * 16 + g;
        int r1 = r0 + 8;
#pragma unroll
        for (int nt = 0; nt < 4; ++nt) {
            int col = n0 + wn * 32 + nt * 8 + tg * 2;
            if (col >= N) continue;   // N even
            float b0 = addb ? bias[col]     : 0.f;
            float b1 = addb ? bias[col + 1] : 0.f;
            *(float2*)&C[(size_t)r0 * ldc + col] =
                make_float2(acc[mt][nt][0] + b0, acc[mt][nt][1] + b1);
            *(float2*)&C[(size_t)r1 * ldc + col] =
                make_float2(acc[mt][nt][2] + b0, acc[mt][nt][3] + b1);
        }
    }
}

// ---------------- LSTM pointwise (c_prev = 0), sums KSPL partials ------------
__device__ __forceinline__ float sigf(float x) { return 1.f / (1.f + expf(-x)); }

__global__ void __launch_bounds__(256) lstm_pointwise4(
    const float* __restrict__ gp,
    const float* __restrict__ b_ih,
    const float* __restrict__ b_hh,
    float* __restrict__ houtf,
    __half* __restrict__ houth)
{
    int idx = blockIdx.x * 256 + threadIdx.x;
    if (idx >= BB * HH) return;
    int b = idx / HH, j = idx - b * HH;
    float gi = 0.f, gg = 0.f, go = 0.f;
#pragma unroll
    for (int z = 0; z < KSPL; ++z) {
        const float* g = gp + (size_t)z * BB * NG + (size_t)b * NG;
        gi += g[j];
        gg += g[HH + j];
        go += g[2 * HH + j];
    }
    gi += b_ih[j]          + b_hh[j];
    gg += b_ih[2 * HH + j] + b_hh[2 * HH + j];
    go += b_ih[3 * HH + j] + b_hh[3 * HH + j];
    float c = sigf(gi) * tanhf(gg);
    float h = sigf(go) * tanhf(c);
    if (houtf) houtf[idx] = h;
    if (houth) houth[idx] = __float2half(h);
}

// ------- scores -> masked softmax -> attended (from imgh) -> x2h -------------
__global__ void __launch_bounds__(128) attn_kernel(const float* __restrict__ wa)
{
    int b = blockIdx.x;
    int tid = threadIdx.x;
    int warp = tid >> 5, lane = tid & 31;
    __shared__ float sc[NB];
    __shared__ float at[NB];
    __shared__ float qb[PP];

    for (int p = tid; p < PP; p += 128) {
        float s = 0.f;
#pragma unroll
        for (int z = 0; z < KSPL; ++z)
            s += g_q[(size_t)z * BB * PP + (size_t)b * PP + p];
        qb[p] = s;
    }
    __syncthreads();

    for (int n = warp; n < NB; n += 4) {
        const float* vp = g_vproj + ((size_t)b * NB + n) * PP;
        float s = 0.f;
        for (int p = lane; p < PP; p += 32)
            s += tanhf(qb[p] + vp[p]) * wa[p];
#pragma unroll
        for (int off = 16; off > 0; off >>= 1)
            s += __shfl_xor_sync(0xffffffffu, s, off);
        if (lane == 0)
            sc[n] = (g_mask[b * NB + n] > 0.f) ? s : -1e9f;
    }
    __syncthreads();

    if (tid == 0) {
        float m = -INFINITY;
        for (int n = 0; n < NB; ++n) m = fmaxf(m, sc[n]);
        float sum = 0.f;
        for (int n = 0; n < NB; ++n) { float e = expf(sc[n] - m); at[n] = e; sum += e; }
        float inv = 1.f / sum;
        for (int n = 0; n < NB; ++n) at[n] *= inv;
    }
    __syncthreads();

    __half* x2 = g_x2h + (size_t)b * K2;
    const __half2* baseh2 = (const __half2*)(g_imgh + (size_t)b * NB * FI);
    for (int f2 = tid; f2 < FI / 2; f2 += 128) {
        float ax = 0.f, ay = 0.f;
#pragma unroll 4
        for (int n = 0; n < NB; ++n) {
            float2 v = __half22float2(baseh2[(size_t)n * (FI / 2) + f2]);
            ax = fmaf(at[n], v.x, ax);
            ay = fmaf(at[n], v.y, ay);
        }
        ((__half2*)x2)[f2] = __floats2half2_rn(ax, ay);
    }
    for (int j = tid; j < HH; j += 128)
        x2[FI + j] = g_h1h[(size_t)b * HH + j];
}

// ---------------- host launcher ----------------------------------------------
extern "C" void kernel_launch(void* const* d_in, const int* in_sizes, int n_in,
                              void* d_out, int out_size)
{
    const float* img   = (const float*)d_in[0];
    const float* emb   = (const float*)d_in[1];
    const float* W_ih1 = (const float*)d_in[2];
    const float* b_ih1 = (const float*)d_in[3];
    const float* b_hh1 = (const float*)d_in[5];
    const float* Wq    = (const float*)d_in[6];
    const float* bq    = (const float*)d_in[7];
    const float* Wv    = (const float*)d_in[8];
    const float* bv    = (const float*)d_in[9];
    const float* wa    = (const float*)d_in[10];
    const float* W_ih2 = (const float*)d_in[11];
    const float* b_ih2 = (const float*)d_in[12];
    const float* b_hh2 = (const float*)d_in[14];
    float* out = (float*)d_out;

    float *p_g, *p_q, *p_v;
    __half *p_x1, *p_x2, *p_h1, *p_w1, *p_w2, *p_wq, *p_wv, *p_img;
    cudaGetSymbolAddress((void**)&p_g,   g_gates);
    cudaGetSymbolAddress((void**)&p_q,   g_q);
    cudaGetSymbolAddress((void**)&p_v,   g_vproj);
    cudaGetSymbolAddress((void**)&p_x1,  g_x1h);
    cudaGetSymbolAddress((void**)&p_x2,  g_x2h);
    cudaGetSymbolAddress((void**)&p_h1,  g_h1h);
    cudaGetSymbolAddress((void**)&p_w1,  g_w1h);
    cudaGetSymbolAddress((void**)&p_w2,  g_w2h);
    cudaGetSymbolAddress((void**)&p_wq,  g_wqh);
    cudaGetSymbolAddress((void**)&p_wv,  g_wvh);
    cudaGetSymbolAddress((void**)&p_img, g_imgh);

    cudaFuncSetAttribute(gemm_h, cudaFuncAttributeMaxDynamicSharedMemorySize, H_SMEM);

    static cudaStream_t s2 = nullptr, s3 = nullptr;
    static cudaEvent_t evF = nullptr, evPool = nullptr, evV = nullptr,
                       evWQ = nullptr, evW2 = nullptr, evImg = nullptr;
    if (!s2) {
        cudaStreamCreateWithFlags(&s2, cudaStreamNonBlocking);
        cudaStreamCreateWithFlags(&s3, cudaStreamNonBlocking);
        cudaEventCreateWithFlags(&evF,    cudaEventDisableTiming);
        cudaEventCreateWithFlags(&evPool, cudaEventDisableTiming);
        cudaEventCreateWithFlags(&evV,    cudaEventDisableTiming);
        cudaEventCreateWithFlags(&evWQ,   cudaEventDisableTiming);
        cudaEventCreateWithFlags(&evW2,   cudaEventDisableTiming);
        cudaEventCreateWithFlags(&evImg,  cudaEventDisableTiming);
    }

    cudaEventRecord(evF, 0);
    cudaStreamWaitEvent(s2, evF, 0);
    cudaStreamWaitEvent(s3, evF, 0);

    // --- s2: Wv cvt -> img cvt+mask (ONLY fp32-img reader) -> vproj ---
    cvt_h<<<512, 256, 0, s2>>>(Wv, FI, p_wv, PP, FI, 0);
    img_cvt_mask<<<BB * NB, 256, 0, s2>>>(img);
    cudaEventRecord(evImg, s2);
    {   // vproj = imgh @ wvh^T + bv : 9216 x 512 x 2048
        dim3 grid(PP / 128, (BB * NB) / 128, 1);
        gemm_h<<<grid, 256, H_SMEM, s2>>>(p_img, FI, p_wv, FI, bv,
                                          p_v, PP, 0, PP, FI, FI);
    }
    cudaEventRecord(evV, s2);

    // --- s3: pool/x1h (after img cvt), Wq + W2 cvts ---
    cudaStreamWaitEvent(s3, evImg, 0);
    {
        dim3 grid(BB, 4);
        pool_build<<<grid, 256, 0, s3>>>(emb);
    }
    cudaEventRecord(evPool, s3);
    cvt_h<<<512, 256, 0, s3>>>(Wq, HH, p_wq, PP, HH, 0);
    cudaEventRecord(evWQ, s3);
    cvt_h<<<2048, 256, 0, s3>>>(W_ih2, FI + 2 * HH, p_w2, NG, K2, 1);
    cudaEventRecord(evW2, s3);

    // --- main chain ---
    cvt_h<<<2048, 256>>>(W_ih1, EE + FI + 2 * HH, p_w1, NG, K1, 1);

    cudaStreamWaitEvent(0, evPool, 0);
    {   // gates1 = x1h @ w1h^T : 256 x 3000 x 3048, split-K 4
        dim3 grid((NG + 127) / 128, BB / 128, KSPL);
        gemm_h<<<grid, 256, H_SMEM>>>(p_x1, K1, p_w1, K1, nullptr,
                                      p_g, NG, (size_t)BB * NG, NG, K1, 768);
    }
    lstm_pointwise4<<<(BB * HH + 255) / 256, 256>>>(p_g, b_ih1, b_hh1,
                                                    nullptr, p_h1);

    cudaStreamWaitEvent(0, evWQ, 0);
    {   // q = h1h @ wqh^T + bq : 256 x 512 x 1000, split-K 4
        dim3 grid(PP / 128, BB / 128, KSPL);
        gemm_h<<<grid, 256, H_SMEM>>>(p_h1, HH, p_wq, HH, bq,
                                      p_q, PP, (size_t)BB * PP, PP, HH, 256);
    }

    cudaStreamWaitEvent(0, evV, 0);
    attn_kernel<<<BB, 128>>>(wa);

    cudaStreamWaitEvent(0, evW2, 0);
    {   // gates2 = x2h @ w2h^T : 256 x 3000 x 3048, split-K 4
        dim3 grid((NG + 127) / 128, BB / 128, KSPL);
        gemm_h<<<grid, 256, H_SMEM>>>(p_x2, K2, p_w2, K2, nullptr,
                                      p_g, NG, (size_t)BB * NG, NG, K2, 768);
    }
    lstm_pointwise4<<<(BB * HH + 255) / 256, 256>>>(p_g, b_ih2, b_hh2,
                                                    out, nullptr);
}

// round 13
// speedup vs baseline: 1.2886x; 1.1969x over previous
#include <cuda_runtime.h>
#include <cuda_fp16.h>
#include <math.h>
#include <stdint.h>

// Problem constants
#define BB 256
#define NB 36
#define FI 2048
#define EE 1000
#define HH 1000
#define PP 512
#define K1 3048
#define K2 3048
#define NG 3000   // 3 live gates * H (f gate dead: c_prev = 0)
#define KSPL 4

// ---------------- scratch ----------------------------------------------------
__device__ __align__(16) __half g_x1h[BB * K1];
__device__ __align__(16) __half g_x2h[BB * K2];
__device__ __align__(16) __half g_h1h[BB * HH];
__device__ __align__(16) __half g_w1h[NG * K1];
__device__ __align__(16) __half g_w2h[NG * K2];
__device__ __align__(16) __half g_wqh[PP * HH];
__device__ __align__(16) __half g_wvh[PP * FI];
__device__ __align__(16) __half g_imgh[BB * NB * FI];
__device__ float g_gates[KSPL * BB * NG];
__device__ float g_q[KSPL * BB * PP];
__device__ float g_vproj[BB * NB * PP];
__device__ float g_mask[BB * NB];
__device__ float g_attw[BB * NB];          // softmax attention weights

// ---------------- fp32 -> fp16 conversion (optionally packing live rows) -----
__global__ void __launch_bounds__(256) cvt_h(
    const float* __restrict__ src, int ld,
    __half* __restrict__ dst,
    int rows, int cols, int remap)
{
    int rowq = cols >> 2;
    int total = rows * rowq;
    int stride = gridDim.x * 256;
    for (int idx = blockIdx.x * 256 + threadIdx.x; idx < total; idx += stride) {
        int row = idx / rowq;
        int c4 = (idx - row * rowq) << 2;
        int sr = remap ? (row < 1000 ? row : row + 1000) : row;
        float4 v = *(const float4*)(src + (size_t)sr * ld + c4);
        __half2* d = (__half2*)(dst + (size_t)row * cols + c4);
        d[0] = __floats2half2_rn(v.x, v.y);
        d[1] = __floats2half2_rn(v.z, v.w);
    }
}

// -------- emb fp32 -> x1h[:, 0:EE] (no dependencies) --------------------------
__global__ void __launch_bounds__(256) emb_cvt(const float* __restrict__ emb)
{
    int idx = blockIdx.x * 256 + threadIdx.x;
    if (idx >= BB * EE) return;
    int b = idx / EE, j = idx - b * EE;
    g_x1h[(size_t)b * K1 + j] = __float2half(emb[idx]);
}

// -------- img fp32->fp16 + per-row |sum| (ONLY fp32-img reader) --------------
__global__ void __launch_bounds__(256) img_cvt_mask(const float* __restrict__ img)
{
    int r = blockIdx.x;
    int tid = threadIdx.x;
    int lane = tid & 31, warp = tid >> 5;
    __shared__ float red[8];

    const float* row = img + (size_t)r * FI;
    float4 v0 = *(const float4*)(row + tid * 8);
    float4 v1 = *(const float4*)(row + tid * 8 + 4);
    float s = fabsf(v0.x) + fabsf(v0.y) + fabsf(v0.z) + fabsf(v0.w)
            + fabsf(v1.x) + fabsf(v1.y) + fabsf(v1.z) + fabsf(v1.w);

    __half2 h0 = __floats2half2_rn(v0.x, v0.y);
    __half2 h1 = __floats2half2_rn(v0.z, v0.w);
    __half2 h2 = __floats2half2_rn(v1.x, v1.y);
    __half2 h3 = __floats2half2_rn(v1.z, v1.w);
    uint4 u;
    u.x = *(uint32_t*)&h0; u.y = *(uint32_t*)&h1;
    u.z = *(uint32_t*)&h2; u.w = *(uint32_t*)&h3;
    *(uint4*)(g_imgh + (size_t)r * FI + tid * 8) = u;

#pragma unroll
    for (int off = 16; off > 0; off >>= 1)
        s += __shfl_xor_sync(0xffffffffu, s, off);
    if (lane == 0) red[warp] = s;
    __syncthreads();
    if (tid == 0) {
        float t = 0.f;
#pragma unroll
        for (int w = 0; w < 8; ++w) t += red[w];
        g_mask[r] = t;
    }
}

// -------- masked mean pool from imgh -> x1h[:, EE:]; grid (B, 4) --------------
__global__ void __launch_bounds__(256) pool_build()
{
    int b = blockIdx.x;
    int chunk = blockIdx.y;
    int tid = threadIdx.x;
    __shared__ float mk[NB];

    if (tid < NB) {
        float m = (g_mask[b * NB + tid] > 0.f) ? 1.f : 0.f;
        mk[tid] = m;
        if (chunk == 0) g_mask[b * NB + tid] = m;
    }
    __syncthreads();

    float cnt = 0.f;
#pragma unroll
    for (int n = 0; n < NB; ++n) cnt += mk[n];
    float inv = 1.f / fmaxf(cnt, 1e-13f);

    const __half2* baseh2 = (const __half2*)(g_imgh + (size_t)b * NB * FI);
    int f2 = chunk * 256 + tid;
    float ax = 0.f, ay = 0.f;
#pragma unroll 6
    for (int n = 0; n < NB; ++n) {
        float2 v = __half22float2(baseh2[(size_t)n * (FI / 2) + f2]);
        ax = fmaf(mk[n], v.x, ax);
        ay = fmaf(mk[n], v.y, ay);
    }
    ((__half2*)(g_x1h + (size_t)b * K1 + EE))[f2] = __floats2half2_rn(ax * inv, ay * inv);
}

// ========== fp16 tensor GEMM: C(+split) = A[M,K] * B[N,K]^T (+bias) ==========
#define H_SMEM (2 * (4096 + 4096) * 2)   // 32 KB

__device__ __forceinline__ void mma_h(float* c, const uint32_t* a, const uint32_t* b) {
    asm volatile(
        "mma.sync.aligned.m16n8k16.row.col.f32.f16.f16.f32 "
        "{%0,%1,%2,%3}, {%4,%5,%6,%7}, {%8,%9}, {%0,%1,%2,%3};"
        : "+f"(c[0]), "+f"(c[1]), "+f"(c[2]), "+f"(c[3])
        : "r"(a[0]), "r"(a[1]), "r"(a[2]), "r"(a[3]), "r"(b[0]), "r"(b[1]));
}

__global__ void __launch_bounds__(256, 2) gemm_h(
    const __half* __restrict__ A, int lda,
    const __half* __restrict__ B, int ldb,
    const float* __restrict__ bias,
    float* __restrict__ C, int ldc, size_t cstride,
    int N, int K, int ksplit)
{
    extern __shared__ __half sh[];
    const int tid  = threadIdx.x;
    const int lane = tid & 31;
    const int warp = tid >> 5;
    const int wm   = warp >> 2;
    const int wn   = warp & 3;
    const int m0   = blockIdx.y * 128;
    const int n0   = blockIdx.x * 128;
    const int kz   = blockIdx.z;
    const int Kst  = kz * ksplit;
    const int Kend = min(K, Kst + ksplit);
    const int nk   = (Kend - Kst + 31) >> 5;
    C += (size_t)kz * cstride;
    const uint32_t sbase = (uint32_t)__cvta_generic_to_shared(sh);

    auto load_tile = [&](int kt, int buf) {
        const int k0 = Kst + kt * 32;
#pragma unroll
        for (int i = 0; i < 2; ++i) {
            int idx = i * 256 + tid;
            int row = idx >> 2, v = idx & 3;
            int sv = v ^ ((row >> 1) & 3);
            int k = k0 + v * 8;
            {
                uint32_t dst = sbase + (uint32_t)(buf * 4096 + row * 32 + sv * 8) * 2;
                const __half* src = A + (size_t)(m0 + row) * lda + (k < Kend ? k : 0);
                int sz = (k < Kend) ? 16 : 0;
                asm volatile("cp.async.cg.shared.global [%0], [%1], 16, %2;\n"
                             :: "r"(dst), "l"(src), "r"(sz));
            }
            {
                int bn = n0 + row;
                uint32_t dst = sbase + (uint32_t)(8192 + buf * 4096 + row * 32 + sv * 8) * 2;
                const __half* src = B + (size_t)(bn < N ? bn : 0) * ldb + (k < Kend ? k : 0);
                int sz = (k < Kend && bn < N) ? 16 : 0;
                asm volatile("cp.async.cg.shared.global [%0], [%1], 16, %2;\n"
                             :: "r"(dst), "l"(src), "r"(sz));
            }
        }
        asm volatile("cp.async.commit_group;");
    };

    float acc[4][4][4];
#pragma unroll
    for (int mt = 0; mt < 4; ++mt)
#pragma unroll
        for (int nt = 0; nt < 4; ++nt)
#pragma unroll
            for (int i = 0; i < 4; ++i) acc[mt][nt][i] = 0.f;

    const int arl = lane & 15;
    const int alv = lane >> 4;
    const int brl = (lane & 7) + ((lane >> 4) << 3);
    const int blv = (lane >> 3) & 1;

    load_tile(0, 0);

    for (int kt = 0; kt < nk; ++kt) {
        asm volatile("cp.async.wait_group 0;");
        __syncthreads();
        if (kt + 1 < nk) load_tile(kt + 1, (kt + 1) & 1);

        const int bo = (kt & 1) * 4096;
#pragma unroll
        for (int s = 0; s < 2; ++s) {
            uint32_t a[4][4], b[4][2];
#pragma unroll
            for (int mt = 0; mt < 4; ++mt) {
                int row = wm * 64 + mt * 16 + arl;
                int sv = (2 * s + alv) ^ ((row >> 1) & 3);
                uint32_t ad = sbase + (uint32_t)(bo + row * 32 + sv * 8) * 2;
                asm volatile(
                    "ldmatrix.sync.aligned.m8n8.x4.shared.b16 {%0,%1,%2,%3}, [%4];"
                    : "=r"(a[mt][0]), "=r"(a[mt][1]), "=r"(a[mt][2]), "=r"(a[mt][3])
                    : "r"(ad));
            }
#pragma unroll
            for (int p = 0; p < 2; ++p) {
                int row = wn * 32 + p * 16 + brl;
                int sv = (2 * s + blv) ^ ((row >> 1) & 3);
                uint32_t ad = sbase + (uint32_t)(8192 + bo + row * 32 + sv * 8) * 2;
                uint32_t r0, r1, r2, r3;
                asm volatile(
                    "ldmatrix.sync.aligned.m8n8.x4.shared.b16 {%0,%1,%2,%3}, [%4];"
                    : "=r"(r0), "=r"(r1), "=r"(r2), "=r"(r3) : "r"(ad));
                b[p * 2][0] = r0;     b[p * 2][1] = r1;
                b[p * 2 + 1][0] = r2; b[p * 2 + 1][1] = r3;
            }
#pragma unroll
            for (int mt = 0; mt < 4; ++mt)
#pragma unroll
                for (int nt = 0; nt < 4; ++nt)
                    mma_h(acc[mt][nt], a[mt], b[nt]);
        }
    }

    const int g = lane >> 2, tg = lane & 3;
    const bool addb = (bias != nullptr) && (kz == 0);
#pragma unroll
    for (int mt = 0; mt < 4; ++mt) {
        int r0 = m0 + wm * 64 + mt * 16 + g;
        int r1 = r0 + 8;
#pragma unroll
        for (int nt = 0; nt < 4; ++nt) {
            int col = n0 + wn * 32 + nt * 8 + tg * 2;
            if (col >= N) continue;
            float b0 = addb ? bias[col]     : 0.f;
            float b1 = addb ? bias[col + 1] : 0.f;
            *(float2*)&C[(size_t)r0 * ldc + col] =
                make_float2(acc[mt][nt][0] + b0, acc[mt][nt][1] + b1);
            *(float2*)&C[(size_t)r1 * ldc + col] =
                make_float2(acc[mt][nt][2] + b0, acc[mt][nt][3] + b1);
        }
    }
}

// ---------------- LSTM pointwise (c_prev = 0), sums KSPL partials ------------
__device__ __forceinline__ float sigf(float x) { return 1.f / (1.f + expf(-x)); }

__global__ void __launch_bounds__(256) lstm_pointwise4(
    const float* __restrict__ gp,
    const float* __restrict__ b_ih,
    const float* __restrict__ b_hh,
    float* __restrict__ houtf,       // optional fp32 out [B,H]
    __half* __restrict__ houth,      // optional fp16 out [B,H]
    __half* __restrict__ houth2,     // optional fp16 out, row stride K2
    int str2)
{
    int idx = blockIdx.x * 256 + threadIdx.x;
    if (idx >= BB * HH) return;
    int b = idx / HH, j = idx - b * HH;
    float gi = 0.f, gg = 0.f, go = 0.f;
#pragma unroll
    for (int z = 0; z < KSPL; ++z) {
        const float* g = gp + (size_t)z * BB * NG + (size_t)b * NG;
        gi += g[j];
        gg += g[HH + j];
        go += g[2 * HH + j];
    }
    gi += b_ih[j]          + b_hh[j];
    gg += b_ih[2 * HH + j] + b_hh[2 * HH + j];
    go += b_ih[3 * HH + j] + b_hh[3 * HH + j];
    float c = sigf(gi) * tanhf(gg);
    float h = sigf(go) * tanhf(c);
    if (houtf)  houtf[idx] = h;
    if (houth)  houth[idx] = __float2half(h);
    if (houth2) houth2[(size_t)b * str2 + j] = __float2half(h);
}

// ------- attention scores -> masked softmax -> g_attw ------------------------
__global__ void __launch_bounds__(128) attn_scores(const float* __restrict__ wa)
{
    int b = blockIdx.x;
    int tid = threadIdx.x;
    int warp = tid >> 5, lane = tid & 31;
    __shared__ float sc[NB];
    __shared__ float qb[PP];

    for (int p = tid; p < PP; p += 128) {
        float s = 0.f;
#pragma unroll
        for (int z = 0; z < KSPL; ++z)
            s += g_q[(size_t)z * BB * PP + (size_t)b * PP + p];
        qb[p] = s;
    }
    __syncthreads();

    for (int n = warp; n < NB; n += 4) {
        const float* vp = g_vproj + ((size_t)b * NB + n) * PP;
        float s = 0.f;
        for (int p = lane; p < PP; p += 32)
            s += tanhf(qb[p] + vp[p]) * wa[p];
#pragma unroll
        for (int off = 16; off > 0; off >>= 1)
            s += __shfl_xor_sync(0xffffffffu, s, off);
        if (lane == 0)
            sc[n] = (g_mask[b * NB + n] > 0.f) ? s : -1e9f;
    }
    __syncthreads();

    if (tid == 0) {
        float m = -INFINITY;
        for (int n = 0; n < NB; ++n) m = fmaxf(m, sc[n]);
        float sum = 0.f;
        float e[NB];
        for (int n = 0; n < NB; ++n) { e[n] = expf(sc[n] - m); sum += e[n]; }
        float inv = 1.f / sum;
        for (int n = 0; n < NB; ++n) g_attw[b * NB + n] = e[n] * inv;
    }
}

// ------- attended = attw @ imgh -> x2h[:, 0:FI]; grid (B, 4) ------------------
__global__ void __launch_bounds__(256) attn_apply()
{
    int b = blockIdx.x;
    int chunk = blockIdx.y;
    int tid = threadIdx.x;
    __shared__ float at[NB];

    if (tid < NB) at[tid] = g_attw[b * NB + tid];
    __syncthreads();

    const __half2* baseh2 = (const __half2*)(g_imgh + (size_t)b * NB * FI);
    int f2 = chunk * 256 + tid;
    float ax = 0.f, ay = 0.f;
#pragma unroll 6
    for (int n = 0; n < NB; ++n) {
        float2 v = __half22float2(baseh2[(size_t)n * (FI / 2) + f2]);
        ax = fmaf(at[n], v.x, ax);
        ay = fmaf(at[n], v.y, ay);
    }
    ((__half2*)(g_x2h + (size_t)b * K2))[f2] = __floats2half2_rn(ax, ay);
}

// ---------------- host launcher ----------------------------------------------
extern "C" void kernel_launch(void* const* d_in, const int* in_sizes, int n_in,
                              void* d_out, int out_size)
{
    const float* img   = (const float*)d_in[0];
    const float* emb   = (const float*)d_in[1];
    const float* W_ih1 = (const float*)d_in[2];
    const float* b_ih1 = (const float*)d_in[3];
    const float* b_hh1 = (const float*)d_in[5];
    const float* Wq    = (const float*)d_in[6];
    const float* bq    = (const float*)d_in[7];
    const float* Wv    = (const float*)d_in[8];
    const float* bv    = (const float*)d_in[9];
    const float* wa    = (const float*)d_in[10];
    const float* W_ih2 = (const float*)d_in[11];
    const float* b_ih2 = (const float*)d_in[12];
    const float* b_hh2 = (const float*)d_in[14];
    float* out = (float*)d_out;

    float *p_g, *p_q, *p_v;
    __half *p_x1, *p_x2, *p_h1, *p_w1, *p_w2, *p_wq, *p_wv, *p_img;
    cudaGetSymbolAddress((void**)&p_g,   g_gates);
    cudaGetSymbolAddress((void**)&p_q,   g_q);
    cudaGetSymbolAddress((void**)&p_v,   g_vproj);
    cudaGetSymbolAddress((void**)&p_x1,  g_x1h);
    cudaGetSymbolAddress((void**)&p_x2,  g_x2h);
    cudaGetSymbolAddress((void**)&p_h1,  g_h1h);
    cudaGetSymbolAddress((void**)&p_w1,  g_w1h);
    cudaGetSymbolAddress((void**)&p_w2,  g_w2h);
    cudaGetSymbolAddress((void**)&p_wq,  g_wqh);
    cudaGetSymbolAddress((void**)&p_wv,  g_wvh);
    cudaGetSymbolAddress((void**)&p_img, g_imgh);

    cudaFuncSetAttribute(gemm_h, cudaFuncAttributeMaxDynamicSharedMemorySize, H_SMEM);

    static cudaStream_t s2 = nullptr, s3 = nullptr;
    static cudaEvent_t evF = nullptr, evPool = nullptr, evV = nullptr,
                       evWQ = nullptr, evImg = nullptr, evW2 = nullptr,
                       evH1 = nullptr, evG2h = nullptr;
    if (!s2) {
        cudaStreamCreateWithFlags(&s2, cudaStreamNonBlocking);
        cudaStreamCreateWithFlags(&s3, cudaStreamNonBlocking);
        cudaEventCreateWithFlags(&evF,    cudaEventDisableTiming);
        cudaEventCreateWithFlags(&evPool, cudaEventDisableTiming);
        cudaEventCreateWithFlags(&evV,    cudaEventDisableTiming);
        cudaEventCreateWithFlags(&evWQ,   cudaEventDisableTiming);
        cudaEventCreateWithFlags(&evImg,  cudaEventDisableTiming);
        cudaEventCreateWithFlags(&evW2,   cudaEventDisableTiming);
        cudaEventCreateWithFlags(&evH1,   cudaEventDisableTiming);
        cudaEventCreateWithFlags(&evG2h,  cudaEventDisableTiming);
    }

    cudaEventRecord(evF, 0);
    cudaStreamWaitEvent(s2, evF, 0);
    cudaStreamWaitEvent(s3, evF, 0);

    // --- s2: img cvt+mask (only fp32-img reader) -> Wv cvt -> vproj ---
    img_cvt_mask<<<BB * NB, 256, 0, s2>>>(img);
    cudaEventRecord(evImg, s2);
    cvt_h<<<512, 256, 0, s2>>>(Wv, FI, p_wv, PP, FI, 0);
    {   // vproj = imgh @ wvh^T + bv : 9216 x 512 x 2048
        dim3 grid(PP / 128, (BB * NB) / 128, 1);
        gemm_h<<<grid, 256, H_SMEM, s2>>>(p_img, FI, p_wv, FI, bv,
                                          p_v, PP, 0, PP, FI, FI);
    }
    cudaEventRecord(evV, s2);

    // --- s3 (part 1): emb cvt, pool, Wq cvt, W2 cvt ---
    emb_cvt<<<(BB * EE + 255) / 256, 256, 0, s3>>>(emb);
    cudaStreamWaitEvent(s3, evImg, 0);
    {
        dim3 grid(BB, 4);
        pool_build<<<grid, 256, 0, s3>>>();
    }
    cudaEventRecord(evPool, s3);
    cvt_h<<<512, 256, 0, s3>>>(Wq, HH, p_wq, PP, HH, 0);
    cudaEventRecord(evWQ, s3);
    cvt_h<<<2048, 256, 0, s3>>>(W_ih2, FI + 2 * HH, p_w2, NG, K2, 1);
    cudaEventRecord(evW2, s3);

    // --- main chain through lstm1 (records evH1 BEFORE s3 waits on it) ---
    cvt_h<<<2048, 256>>>(W_ih1, EE + FI + 2 * HH, p_w1, NG, K1, 1);

    cudaStreamWaitEvent(0, evPool, 0);
    {   // gates1 = x1h @ w1h^T : 256 x 3000 x 3048, split-K 4
        dim3 grid((NG + 127) / 128, BB / 128, KSPL);
        gemm_h<<<grid, 256, H_SMEM>>>(p_x1, K1, p_w1, K1, nullptr,
                                      p_g, NG, (size_t)BB * NG, NG, K1, 768);
    }
    // lstm1: writes h1h (for q GEMM) AND x2h[:, FI:FI+H] (h1 slice of x2)
    lstm_pointwise4<<<(BB * HH + 255) / 256, 256>>>(p_g, b_ih1, b_hh1,
                                                    nullptr, p_h1, p_x2 + FI, K2);
    cudaEventRecord(evH1, 0);

    // --- s3 (part 2): gates2 h1-slice, K in [2048,3048) -> partial z=3 ---
    cudaStreamWaitEvent(s3, evH1, 0);   // evH1 recorded above in program order
    {
        dim3 grid((NG + 127) / 128, BB / 128, 1);
        gemm_h<<<grid, 256, H_SMEM, s3>>>(p_x2 + FI, K2, p_w2 + FI, K2, nullptr,
                                          p_g + (size_t)3 * BB * NG, NG, 0,
                                          NG, 1000, 1000);
    }
    cudaEventRecord(evG2h, s3);

    // --- main chain continues ---
    cudaStreamWaitEvent(0, evWQ, 0);
    {   // q = h1h @ wqh^T + bq : 256 x 512 x 1000, split-K 4
        dim3 grid(PP / 128, BB / 128, KSPL);
        gemm_h<<<grid, 256, H_SMEM>>>(p_h1, HH, p_wq, HH, bq,
                                      p_q, PP, (size_t)BB * PP, PP, HH, 256);
    }

    cudaStreamWaitEvent(0, evV, 0);
    attn_scores<<<BB, 128>>>(wa);
    {
        dim3 grid(BB, 4);
        attn_apply<<<grid, 256>>>();
    }

    // gates2 attended-slice: K in [0,2048), 3 z-splits of 688 -> partials z=0..2
    cudaStreamWaitEvent(0, evW2, 0);
    cudaStreamWaitEvent(0, evG2h, 0);
    {
        dim3 grid((NG + 127) / 128, BB / 128, 3);
        gemm_h<<<grid, 256, H_SMEM>>>(p_x2, K2, p_w2, K2, nullptr,
                                      p_g, NG, (size_t)BB * NG, NG, 2048, 688);
    }
    lstm_pointwise4<<<(BB * HH + 255) / 256, 256>>>(p_g, b_ih2, b_hh2,
                                                    out, nullptr, nullptr, 0);
}

// round 15
// speedup vs baseline: 1.3306x; 1.0326x over previous
#include <cuda_runtime.h>
#include <cuda_fp16.h>
#include <math.h>
#include <stdint.h>

// Problem constants
#define BB 256
#define NB 36
#define FI 2048
#define EE 1000
#define HH 1000
#define PP 512
#define K1 3048
#define K2 3048
#define NG 3000   // 3 live gates * H (f gate dead: c_prev = 0)
#define KSPL 4

// ---------------- scratch ----------------------------------------------------
__device__ __align__(16) __half g_x1h[BB * K1];
__device__ __align__(16) __half g_x2h[BB * K2];
__device__ __align__(16) __half g_h1h[BB * HH];
__device__ __align__(16) __half g_w1h[NG * K1];
__device__ __align__(16) __half g_w2h[NG * K2];
__device__ __align__(16) __half g_wqh[PP * HH];
__device__ __align__(16) __half g_wvh[PP * FI];
__device__ __align__(16) __half g_imgh[BB * NB * FI];
__device__ float g_gates[KSPL * BB * NG];
__device__ float g_q[KSPL * BB * PP];
__device__ float g_vproj[BB * NB * PP];
__device__ float g_mask[BB * NB];
__device__ float g_attw[BB * NB];

// ---------------- fp32 -> fp16 conversion (optionally packing live rows) -----
__global__ void __launch_bounds__(256) cvt_h(
    const float* __restrict__ src, int ld,
    __half* __restrict__ dst,
    int rows, int cols, int remap)
{
    int rowq = cols >> 2;
    int total = rows * rowq;
    int stride = gridDim.x * 256;
    for (int idx = blockIdx.x * 256 + threadIdx.x; idx < total; idx += stride) {
        int row = idx / rowq;
        int c4 = (idx - row * rowq) << 2;
        int sr = remap ? (row < 1000 ? row : row + 1000) : row;
        float4 v = *(const float4*)(src + (size_t)sr * ld + c4);
        __half2* d = (__half2*)(dst + (size_t)row * cols + c4);
        d[0] = __floats2half2_rn(v.x, v.y);
        d[1] = __floats2half2_rn(v.z, v.w);
    }
}

// -------- emb fp32 -> x1h[:, 0:EE] --------------------------------------------
__global__ void __launch_bounds__(256) emb_cvt(const float* __restrict__ emb)
{
    int idx = blockIdx.x * 256 + threadIdx.x;
    if (idx >= BB * EE) return;
    int b = idx / EE, j = idx - b * EE;
    g_x1h[(size_t)b * K1 + j] = __float2half(emb[idx]);
}

// -------- img fp32->fp16 + per-row |sum|; one block per (b,n) row + offset ---
__global__ void __launch_bounds__(256) img_cvt_mask(
    const float* __restrict__ img, int roff)
{
    int r = blockIdx.x + roff;
    int tid = threadIdx.x;
    int lane = tid & 31, warp = tid >> 5;
    __shared__ float red[8];

    const float* row = img + (size_t)r * FI;
    float4 v0 = *(const float4*)(row + tid * 8);
    float4 v1 = *(const float4*)(row + tid * 8 + 4);
    float s = fabsf(v0.x) + fabsf(v0.y) + fabsf(v0.z) + fabsf(v0.w)
            + fabsf(v1.x) + fabsf(v1.y) + fabsf(v1.z) + fabsf(v1.w);

    __half2 h0 = __floats2half2_rn(v0.x, v0.y);
    __half2 h1 = __floats2half2_rn(v0.z, v0.w);
    __half2 h2 = __floats2half2_rn(v1.x, v1.y);
    __half2 h3 = __floats2half2_rn(v1.z, v1.w);
    uint4 u;
    u.x = *(uint32_t*)&h0; u.y = *(uint32_t*)&h1;
    u.z = *(uint32_t*)&h2; u.w = *(uint32_t*)&h3;
    *(uint4*)(g_imgh + (size_t)r * FI + tid * 8) = u;

#pragma unroll
    for (int off = 16; off > 0; off >>= 1)
        s += __shfl_xor_sync(0xffffffffu, s, off);
    if (lane == 0) red[warp] = s;
    __syncthreads();
    if (tid == 0) {
        float t = 0.f;
#pragma unroll
        for (int w = 0; w < 8; ++w) t += red[w];
        g_mask[r] = t;
    }
}

// -------- masked mean pool from imgh -> x1h[:, EE:]; grid (B, 4) --------------
__global__ void __launch_bounds__(256) pool_build()
{
    int b = blockIdx.x;
    int chunk = blockIdx.y;
    int tid = threadIdx.x;
    __shared__ float mk[NB];

    if (tid < NB) {
        float m = (g_mask[b * NB + tid] > 0.f) ? 1.f : 0.f;
        mk[tid] = m;
        if (chunk == 0) g_mask[b * NB + tid] = m;
    }
    __syncthreads();

    float cnt = 0.f;
#pragma unroll
    for (int n = 0; n < NB; ++n) cnt += mk[n];
    float inv = 1.f / fmaxf(cnt, 1e-13f);

    const __half2* baseh2 = (const __half2*)(g_imgh + (size_t)b * NB * FI);
    int f2 = chunk * 256 + tid;
    float ax = 0.f, ay = 0.f;
#pragma unroll 6
    for (int n = 0; n < NB; ++n) {
        float2 v = __half22float2(baseh2[(size_t)n * (FI / 2) + f2]);
        ax = fmaf(mk[n], v.x, ax);
        ay = fmaf(mk[n], v.y, ay);
    }
    ((__half2*)(g_x1h + (size_t)b * K1 + EE))[f2] = __floats2half2_rn(ax * inv, ay * inv);
}

// ========== fp16 tensor GEMM: C(+split) = A[M,K] * B[N,K]^T (+bias) ==========
#define H_SMEM (2 * (4096 + 4096) * 2)   // 32 KB

__device__ __forceinline__ void mma_h(float* c, const uint32_t* a, const uint32_t* b) {
    asm volatile(
        "mma.sync.aligned.m16n8k16.row.col.f32.f16.f16.f32 "
        "{%0,%1,%2,%3}, {%4,%5,%6,%7}, {%8,%9}, {%0,%1,%2,%3};"
        : "+f"(c[0]), "+f"(c[1]), "+f"(c[2]), "+f"(c[3])
        : "r"(a[0]), "r"(a[1]), "r"(a[2]), "r"(a[3]), "r"(b[0]), "r"(b[1]));
}

__global__ void __launch_bounds__(256, 2) gemm_h(
    const __half* __restrict__ A, int lda,
    const __half* __restrict__ B, int ldb,
    const float* __restrict__ bias,
    float* __restrict__ C, int ldc, size_t cstride,
    int N, int K, int ksplit)
{
    extern __shared__ __half sh[];
    const int tid  = threadIdx.x;
    const int lane = tid & 31;
    const int warp = tid >> 5;
    const int wm   = warp >> 2;
    const int wn   = warp & 3;
    const int m0   = blockIdx.y * 128;
    const int n0   = blockIdx.x * 128;
    const int kz   = blockIdx.z;
    const int Kst  = kz * ksplit;
    const int Kend = min(K, Kst + ksplit);
    const int nk   = (Kend - Kst + 31) >> 5;
    C += (size_t)kz * cstride;
    const uint32_t sbase = (uint32_t)__cvta_generic_to_shared(sh);

    auto load_tile = [&](int kt, int buf) {
        const int k0 = Kst + kt * 32;
#pragma unroll
        for (int i = 0; i < 2; ++i) {
            int idx = i * 256 + tid;
            int row = idx >> 2, v = idx & 3;
            int sv = v ^ ((row >> 1) & 3);
            int k = k0 + v * 8;
            {
                uint32_t dst = sbase + (uint32_t)(buf * 4096 + row * 32 + sv * 8) * 2;
                const __half* src = A + (size_t)(m0 + row) * lda + (k < Kend ? k : 0);
                int sz = (k < Kend) ? 16 : 0;
                asm volatile("cp.async.cg.shared.global [%0], [%1], 16, %2;\n"
                             :: "r"(dst), "l"(src), "r"(sz));
            }
            {
                int bn = n0 + row;
                uint32_t dst = sbase + (uint32_t)(8192 + buf * 4096 + row * 32 + sv * 8) * 2;
                const __half* src = B + (size_t)(bn < N ? bn : 0) * ldb + (k < Kend ? k : 0);
                int sz = (k < Kend && bn < N) ? 16 : 0;
                asm volatile("cp.async.cg.shared.global [%0], [%1], 16, %2;\n"
                             :: "r"(dst), "l"(src), "r"(sz));
            }
        }
        asm volatile("cp.async.commit_group;");
    };

    float acc[4][4][4];
#pragma unroll
    for (int mt = 0; mt < 4; ++mt)
#pragma unroll
        for (int nt = 0; nt < 4; ++nt)
#pragma unroll
            for (int i = 0; i < 4; ++i) acc[mt][nt][i] = 0.f;

    const int arl = lane & 15;
    const int alv = lane >> 4;
    const int brl = (lane & 7) + ((lane >> 4) << 3);
    const int blv = (lane >> 3) & 1;

    load_tile(0, 0);

    for (int kt = 0; kt < nk; ++kt) {
        asm volatile("cp.async.wait_group 0;");
        __syncthreads();
        if (kt + 1 < nk) load_tile(kt + 1, (kt + 1) & 1);

        const int bo = (kt & 1) * 4096;
#pragma unroll
        for (int s = 0; s < 2; ++s) {
            uint32_t a[4][4], b[4][2];
#pragma unroll
            for (int mt = 0; mt < 4; ++mt) {
                int row = wm * 64 + mt * 16 + arl;
                int sv = (2 * s + alv) ^ ((row >> 1) & 3);
                uint32_t ad = sbase + (uint32_t)(bo + row * 32 + sv * 8) * 2;
                asm volatile(
                    "ldmatrix.sync.aligned.m8n8.x4.shared.b16 {%0,%1,%2,%3}, [%4];"
                    : "=r"(a[mt][0]), "=r"(a[mt][1]), "=r"(a[mt][2]), "=r"(a[mt][3])
                    : "r"(ad));
            }
#pragma unroll
            for (int p = 0; p < 2; ++p) {
                int row = wn * 32 + p * 16 + brl;
                int sv = (2 * s + blv) ^ ((row >> 1) & 3);
                uint32_t ad = sbase + (uint32_t)(8192 + bo + row * 32 + sv * 8) * 2;
                uint32_t r0, r1, r2, r3;
                asm volatile(
                    "ldmatrix.sync.aligned.m8n8.x4.shared.b16 {%0,%1,%2,%3}, [%4];"
                    : "=r"(r0), "=r"(r1), "=r"(r2), "=r"(r3) : "r"(ad));
                b[p * 2][0] = r0;     b[p * 2][1] = r1;
                b[p * 2 + 1][0] = r2; b[p * 2 + 1][1] = r3;
            }
#pragma unroll
            for (int mt = 0; mt < 4; ++mt)
#pragma unroll
                for (int nt = 0; nt < 4; ++nt)
                    mma_h(acc[mt][nt], a[mt], b[nt]);
        }
    }

    const int g = lane >> 2, tg = lane & 3;
    const bool addb = (bias != nullptr) && (kz == 0);
#pragma unroll
    for (int mt = 0; mt < 4; ++mt) {
        int r0 = m0 + wm * 64 + mt * 16 + g;
        int r1 = r0 + 8;
#pragma unroll
        for (int nt = 0; nt < 4; ++nt) {
            int col = n0 + wn * 32 + nt * 8 + tg * 2;
            if (col >= N) continue;
            float b0 = addb ? bias[col]     : 0.f;
            float b1 = addb ? bias[col + 1] : 0.f;
            *(float2*)&C[(size_t)r0 * ldc + col] =
                make_float2(acc[mt][nt][0] + b0, acc[mt][nt][1] + b1);
            *(float2*)&C[(size_t)r1 * ldc + col] =
                make_float2(acc[mt][nt][2] + b0, acc[mt][nt][3] + b1);
        }
    }
}

// ---------------- LSTM pointwise (c_prev = 0), sums KSPL partials ------------
__device__ __forceinline__ float sigf(float x) { return 1.f / (1.f + expf(-x)); }

__global__ void __launch_bounds__(256) lstm_pointwise4(
    const float* __restrict__ gp,
    const float* __restrict__ b_ih,
    const float* __restrict__ b_hh,
    float* __restrict__ houtf,
    __half* __restrict__ houth,
    __half* __restrict__ houth2,
    int str2)
{
    int idx = blockIdx.x * 256 + threadIdx.x;
    if (idx >= BB * HH) return;
    int b = idx / HH, j = idx - b * HH;
    float gi = 0.f, gg = 0.f, go = 0.f;
#pragma unroll
    for (int z = 0; z < KSPL; ++z) {
        const float* g = gp + (size_t)z * BB * NG + (size_t)b * NG;
        gi += g[j];
        gg += g[HH + j];
        go += g[2 * HH + j];
    }
    gi += b_ih[j]          + b_hh[j];
    gg += b_ih[2 * HH + j] + b_hh[2 * HH + j];
    go += b_ih[3 * HH + j] + b_hh[3 * HH + j];
    float c = sigf(gi) * tanhf(gg);
    float h = sigf(go) * tanhf(c);
    if (houtf)  houtf[idx] = h;
    if (houth)  houth[idx] = __float2half(h);
    if (houth2) houth2[(size_t)b * str2 + j] = __float2half(h);
}

// ------- attention scores -> masked softmax -> g_attw ------------------------
__global__ void __launch_bounds__(128) attn_scores(const float* __restrict__ wa)
{
    int b = blockIdx.x;
    int tid = threadIdx.x;
    int warp = tid >> 5, lane = tid & 31;
    __shared__ float sc[NB];
    __shared__ float qb[PP];

    for (int p = tid; p < PP; p += 128) {
        float s = 0.f;
#pragma unroll
        for (int z = 0; z < KSPL; ++z)
            s += g_q[(size_t)z * BB * PP + (size_t)b * PP + p];
        qb[p] = s;
    }
    __syncthreads();

    for (int n = warp; n < NB; n += 4) {
        const float* vp = g_vproj + ((size_t)b * NB + n) * PP;
        float s = 0.f;
        for (int p = lane; p < PP; p += 32)
            s += tanhf(qb[p] + vp[p]) * wa[p];
#pragma unroll
        for (int off = 16; off > 0; off >>= 1)
            s += __shfl_xor_sync(0xffffffffu, s, off);
        if (lane == 0)
            sc[n] = (g_mask[b * NB + n] > 0.f) ? s : -1e9f;
    }
    __syncthreads();

    if (tid == 0) {
        float m = -INFINITY;
        for (int n = 0; n < NB; ++n) m = fmaxf(m, sc[n]);
        float sum = 0.f;
        float e[NB];
        for (int n = 0; n < NB; ++n) { e[n] = expf(sc[n] - m); sum += e[n]; }
        float inv = 1.f / sum;
        for (int n = 0; n < NB; ++n) g_attw[b * NB + n] = e[n] * inv;
    }
}

// ------- attended = attw @ imgh -> x2h[:, 0:FI]; grid (B, 4) ------------------
__global__ void __launch_bounds__(256) attn_apply()
{
    int b = blockIdx.x;
    int chunk = blockIdx.y;
    int tid = threadIdx.x;
    __shared__ float at[NB];

    if (tid < NB) at[tid] = g_attw[b * NB + tid];
    __syncthreads();

    const __half2* baseh2 = (const __half2*)(g_imgh + (size_t)b * NB * FI);
    int f2 = chunk * 256 + tid;
    float ax = 0.f, ay = 0.f;
#pragma unroll 6
    for (int n = 0; n < NB; ++n) {
        float2 v = __half22float2(baseh2[(size_t)n * (FI / 2) + f2]);
        ax = fmaf(at[n], v.x, ax);
        ay = fmaf(at[n], v.y, ay);
    }
    ((__half2*)(g_x2h + (size_t)b * K2))[f2] = __floats2half2_rn(ax, ay);
}

// ---------------- host launcher ----------------------------------------------
extern "C" void kernel_launch(void* const* d_in, const int* in_sizes, int n_in,
                              void* d_out, int out_size)
{
    const float* img   = (const float*)d_in[0];
    const float* emb   = (const float*)d_in[1];
    const float* W_ih1 = (const float*)d_in[2];
    const float* b_ih1 = (const float*)d_in[3];
    const float* b_hh1 = (const float*)d_in[5];
    const float* Wq    = (const float*)d_in[6];
    const float* bq    = (const float*)d_in[7];
    const float* Wv    = (const float*)d_in[8];
    const float* bv    = (const float*)d_in[9];
    const float* wa    = (const float*)d_in[10];
    const float* W_ih2 = (const float*)d_in[11];
    const float* b_ih2 = (const float*)d_in[12];
    const float* b_hh2 = (const float*)d_in[14];
    float* out = (float*)d_out;

    float *p_g, *p_q, *p_v;
    __half *p_x1, *p_x2, *p_h1, *p_w1, *p_w2, *p_wq, *p_wv, *p_img;
    cudaGetSymbolAddress((void**)&p_g,   g_gates);
    cudaGetSymbolAddress((void**)&p_q,   g_q);
    cudaGetSymbolAddress((void**)&p_v,   g_vproj);
    cudaGetSymbolAddress((void**)&p_x1,  g_x1h);
    cudaGetSymbolAddress((void**)&p_x2,  g_x2h);
    cudaGetSymbolAddress((void**)&p_h1,  g_h1h);
    cudaGetSymbolAddress((void**)&p_w1,  g_w1h);
    cudaGetSymbolAddress((void**)&p_w2,  g_w2h);
    cudaGetSymbolAddress((void**)&p_wq,  g_wqh);
    cudaGetSymbolAddress((void**)&p_wv,  g_wvh);
    cudaGetSymbolAddress((void**)&p_img, g_imgh);

    cudaFuncSetAttribute(gemm_h, cudaFuncAttributeMaxDynamicSharedMemorySize, H_SMEM);

    static cudaStream_t s2 = nullptr, s3 = nullptr;
    static cudaEvent_t evF = nullptr, evIA = nullptr, evWv = nullptr,
                       evPool = nullptr, evW2 = nullptr, evH1 = nullptr,
                       evG2h = nullptr, evVA = nullptr, evVB = nullptr;
    if (!s2) {
        cudaStreamCreateWithFlags(&s2, cudaStreamNonBlocking);
        cudaStreamCreateWithFlags(&s3, cudaStreamNonBlocking);
        cudaEventCreateWithFlags(&evF,    cudaEventDisableTiming);
        cudaEventCreateWithFlags(&evIA,   cudaEventDisableTiming);
        cudaEventCreateWithFlags(&evWv,   cudaEventDisableTiming);
        cudaEventCreateWithFlags(&evPool, cudaEventDisableTiming);
        cudaEventCreateWithFlags(&evW2,   cudaEventDisableTiming);
        cudaEventCreateWithFlags(&evH1,   cudaEventDisableTiming);
        cudaEventCreateWithFlags(&evG2h,  cudaEventDisableTiming);
        cudaEventCreateWithFlags(&evVA,   cudaEventDisableTiming);
        cudaEventCreateWithFlags(&evVB,   cudaEventDisableTiming);
    }

    const int HALF_R = (BB * NB) / 2;   // 4608 rows = batches [0,128) / [128,256)

    cudaEventRecord(evF, 0);
    cudaStreamWaitEvent(s2, evF, 0);
    cudaStreamWaitEvent(s3, evF, 0);

    // --- s3: Wv cvt (gates both vproj halves) ---
    cvt_h<<<512, 256, 0, s3>>>(Wv, FI, p_wv, PP, FI, 0);
    cudaEventRecord(evWv, s3);

    // --- s2: imgA -> imgB -> pool -> vprojB ---
    img_cvt_mask<<<HALF_R, 256, 0, s2>>>(img, 0);
    cudaEventRecord(evIA, s2);
    img_cvt_mask<<<HALF_R, 256, 0, s2>>>(img, HALF_R);
    {
        dim3 grid(BB, 4);
        pool_build<<<grid, 256, 0, s2>>>();
    }
    cudaEventRecord(evPool, s2);
    cudaStreamWaitEvent(s2, evWv, 0);
    {   // vproj rows [4608, 9216)
        dim3 grid(PP / 128, HALF_R / 128, 1);
        gemm_h<<<grid, 256, H_SMEM, s2>>>(p_img + (size_t)HALF_R * FI, FI,
                                          p_wv, FI, bv,
                                          p_v + (size_t)HALF_R * PP, PP, 0,
                                          PP, FI, FI);
    }
    cudaEventRecord(evVB, s2);

    // --- s3: vprojA after imgA ---
    cudaStreamWaitEvent(s3, evIA, 0);
    {   // vproj rows [0, 4608)
        dim3 grid(PP / 128, HALF_R / 128, 1);
        gemm_h<<<grid, 256, H_SMEM, s3>>>(p_img, FI, p_wv, FI, bv,
                                          p_v, PP, 0, PP, FI, FI);
    }
    cudaEventRecord(evVA, s3);

    // --- main: all remaining conversions fit in the pre-gates1 idle window ---
    emb_cvt<<<(BB * EE + 255) / 256, 256>>>(emb);
    cvt_h<<<2048, 256>>>(W_ih1, EE + FI + 2 * HH, p_w1, NG, K1, 1);
    cvt_h<<<512, 256>>>(Wq, HH, p_wq, PP, HH, 0);
    cvt_h<<<2048, 256>>>(W_ih2, FI + 2 * HH, p_w2, NG, K2, 1);
    cudaEventRecord(evW2, 0);

    cudaStreamWaitEvent(0, evPool, 0);
    {   // gates1 = x1h @ w1h^T : split-K 4
        dim3 grid((NG + 127) / 128, BB / 128, KSPL);
        gemm_h<<<grid, 256, H_SMEM>>>(p_x1, K1, p_w1, K1, nullptr,
                                      p_g, NG, (size_t)BB * NG, NG, K1, 768);
    }
    lstm_pointwise4<<<(BB * HH + 255) / 256, 256>>>(p_g, b_ih1, b_hh1,
                                                    nullptr, p_h1, p_x2 + FI, K2);
    cudaEventRecord(evH1, 0);

    // --- s3 part 2: gates2 h1-slice (K in [2048,3048)) -> partial z=3 ---
    cudaStreamWaitEvent(s3, evH1, 0);
    cudaStreamWaitEvent(s3, evW2, 0);
    {
        dim3 grid((NG + 127) / 128, BB / 128, 1);
        gemm_h<<<grid, 256, H_SMEM, s3>>>(p_x2 + FI, K2, p_w2 + FI, K2, nullptr,
                                          p_g + (size_t)3 * BB * NG, NG, 0,
                                          NG, 1000, 1000);
    }
    cudaEventRecord(evG2h, s3);

    // --- main continues (Wq cvt is main-ordered; no extra wait needed) ---
    {   // q = h1h @ wqh^T + bq : split-K 4
        dim3 grid(PP / 128, BB / 128, KSPL);
        gemm_h<<<grid, 256, H_SMEM>>>(p_h1, HH, p_wq, HH, bq,
                                      p_q, PP, (size_t)BB * PP, PP, HH, 256);
    }

    cudaStreamWaitEvent(0, evVA, 0);
    cudaStreamWaitEvent(0, evVB, 0);
    attn_scores<<<BB, 128>>>(wa);
    {
        dim3 grid(BB, 4);
        attn_apply<<<grid, 256>>>();
    }

    // gates2 attended-slice: K in [0,2048), 3 z-splits of 688 -> partials 0..2
    cudaStreamWaitEvent(0, evG2h, 0);
    {
        dim3 grid((NG + 127) / 128, BB / 128, 3);
        gemm_h<<<grid, 256, H_SMEM>>>(p_x2, K2, p_w2, K2, nullptr,
                                      p_g, NG, (size_t)BB * NG, NG, 2048, 688);
    }
    lstm_pointwise4<<<(BB * HH + 255) / 256, 256>>>(p_g, b_ih2, b_hh2,
                                                    out, nullptr, nullptr, 0);
}